// round 14
// baseline (speedup 1.0000x reference)
#include <cuda_runtime.h>
#include <cuda_fp16.h>
#include <math.h>
#include <stdint.h>

// TreeLSTM — round 14: R13 GEMM config (64x128 CTA, warp 32x32, 24 warps/SM)
// + k_final fused into the o-gate epilogue + fc zeroing fused into hs_sum.
//
//  k_wsplit  : W -> [N][K] fp16
//  k_hs_sum  : segment sum -> fp16; child_hs -> fp16; zero fc rows
//  k_gemm<0> : fc[seg[e]] += sigmoid(hs@Wf^T + bf) * cs       (atomics)
//  k_gemm<1> : gates i (->iact) and g (->gact)
//  k_gemm<2> : gate o + fused LSTM final: h, c -> out
//  (no k_final)

#define D    256
#define D3   768
#define MAX_P 100000
#define MAX_E 400000

// ---------------- scratch ----------------
__device__ float g_fc[(size_t)MAX_P * D];
__device__ float g_iact[(size_t)MAX_P * D];
__device__ float g_gact[(size_t)MAX_P * D];
__device__ __half g_hs16[(size_t)MAX_E * D];     // child_hs as fp16
__device__ __half g_hssum16[(size_t)MAX_P * D];  // hs_sum as fp16
__device__ __half g_wf16[D * D];                 // W_f^T fp16
__device__ __half g_wg16[D3 * D];                // W_gates^T fp16

// ---------------- helpers ----------------
__device__ __forceinline__ uint32_t smem_to_u32(const void* p) {
    uint32_t a;
    asm("{ .reg .u64 t; cvta.to.shared.u64 t, %1; cvt.u32.u64 %0, t; }" : "=r"(a) : "l"(p));
    return a;
}
__device__ __forceinline__ float sigmoid_f(float x) { return 1.0f / (1.0f + __expf(-x)); }

#define CP_ASYNC16(dst, src) \
    asm volatile("cp.async.cg.shared.global [%0], [%1], 16;" :: "r"(dst), "l"(src))
#define CP_COMMIT() asm volatile("cp.async.commit_group;")
#define CP_WAIT_1() asm volatile("cp.async.wait_group 1;")

__device__ __forceinline__ void ldsm_x4(uint32_t a[4], uint32_t addr) {
    asm volatile("ldmatrix.sync.aligned.m8n8.x4.shared.b16 {%0,%1,%2,%3}, [%4];"
        : "=r"(a[0]), "=r"(a[1]), "=r"(a[2]), "=r"(a[3]) : "r"(addr));
}
__device__ __forceinline__ void mma_f16(float c[4], const uint32_t a[4], const uint32_t b[2]) {
    asm volatile(
        "mma.sync.aligned.m16n8k16.row.col.f32.f16.f16.f32 "
        "{%0,%1,%2,%3}, {%4,%5,%6,%7}, {%8,%9}, {%0,%1,%2,%3};"
        : "+f"(c[0]), "+f"(c[1]), "+f"(c[2]), "+f"(c[3])
        : "r"(a[0]), "r"(a[1]), "r"(a[2]), "r"(a[3]), "r"(b[0]), "r"(b[1]));
}

// Swizzled byte offset in a [rows][64 fp16] tile: 128B rows, 8 chunks of 16B.
__device__ __forceinline__ uint32_t swz8(int row, int ch) {
    return (uint32_t)(row * 128 + (((ch) ^ ((row) & 7)) << 4));
}

// ---------------------------------------------------------------------------
// k_wsplit: W[256 x ncols] -> T [ncols][256] fp16 (transpose + round)
// ---------------------------------------------------------------------------
__global__ void k_wsplit(const float* __restrict__ W, int ncols,
                         __half* __restrict__ T) {
    __shared__ float s[32][33];
    int nt = blockIdx.x * 32, kt = blockIdx.y * 32;
    int tx = threadIdx.x & 31, ty = threadIdx.x >> 5;
    #pragma unroll
    for (int i = 0; i < 4; ++i)
        s[ty + i * 8][tx] = W[(size_t)(kt + ty + i * 8) * ncols + nt + tx];
    __syncthreads();
    #pragma unroll
    for (int i = 0; i < 4; ++i) {
        int n = nt + ty + i * 8;
        int k = kt + tx;
        T[(size_t)n * D + k] = __float2half_rn(s[tx][ty + i * 8]);
    }
}

// ---------------------------------------------------------------------------
// k_hs_sum: segment sum -> fp16; child_hs -> fp16; zero this parent's fc row.
// ---------------------------------------------------------------------------
__global__ void k_hs_sum(const float* __restrict__ hs, const int* __restrict__ seg,
                         int E, __half* __restrict__ hs16,
                         __half* __restrict__ sum16, float* __restrict__ fc) {
    __shared__ int sb2[2];
    int p = blockIdx.x;
    if (threadIdx.x < 2) {
        int target = p + (int)threadIdx.x;
        int lo = 0, hi = E;
        while (lo < hi) { int m = (lo + hi) >> 1; if (seg[m] < target) lo = m + 1; else hi = m; }
        sb2[threadIdx.x] = lo;
    }
    fc[(size_t)p * D + threadIdx.x] = 0.0f;   // fused memset
    __syncthreads();
    int lo = sb2[0], hi = sb2[1];
    float s = 0.0f;
    for (int e = lo; e < hi; ++e) {
        float v = hs[(size_t)e * D + threadIdx.x];
        s += v;
        hs16[(size_t)e * D + threadIdx.x] = __float2half_rn(v);
    }
    sum16[(size_t)p * D + threadIdx.x] = __float2half_rn(s);
}

// ---------------------------------------------------------------------------
// k_gemm<MODE>: single-pass fp16 GEMM. CTA 64x128, 256 thr, 8 warps (2m x 4n),
// warp tile 32x32, BK=64, 4 chunks, 3-stage cp.async, 3 CTAs/SM.
// MODE 0: fgemm; blockIdx.x = nhalf.  atomicAdd fc[seg[row]] += sig(v)*cc.
// MODE 1: gates i,g; blockIdx.x: bit0 = nhalf, bit1 -> gate 0 or 2.
//         gate 0 -> sig -> o0 (iact); gate 2 -> tanh -> o2 (gact).
// MODE 2: gate o (gate=1); blockIdx.x = nhalf. Fused LSTM final epilogue:
//         c = iact*gact + fc; h = sig(v)*tanh(c); out[h | c].
// ---------------------------------------------------------------------------
#define SM_A    0            // 64 rows x 64 fp16  = 8192
#define SM_B    8192         // 128 rows x 64 fp16 = 16384
#define SM_STAGE 24576
#define SM_TOTAL (3 * SM_STAGE + 512)

template <int MODE>
__global__ void __launch_bounds__(256, 3)
k_gemm(const __half* __restrict__ A16,
       const __half* __restrict__ Bt_g,
       const float* __restrict__ bias_g,
       const float* __restrict__ cc,
       const int* __restrict__ seg,
       float* __restrict__ fc,
       float* __restrict__ o0, float* __restrict__ o1, float* __restrict__ o2,
       float* __restrict__ out, int total,
       int Mtot) {
    extern __shared__ char smem[];
    const uint32_t sb = smem_to_u32(smem);
    const int tid  = threadIdx.x;
    const int lane = tid & 31;
    const int wid  = tid >> 5;
    const int wm   = wid >> 2;          // 0..1 (32 rows each)
    const int wn   = wid & 3;           // 0..3 (32 cols each)
    const int bm   = blockIdx.y * 64;
    const int gate  = (MODE == 1) ? ((int)blockIdx.x & 2) : (MODE == 2 ? 1 : 0);
    const int nhalf = (MODE == 0 || MODE == 2) ? (int)blockIdx.x
                                               : ((int)blockIdx.x & 1);

    const __half* Bt = Bt_g + ((size_t)gate * 256 + nhalf * 128) * D;
    const float* bias = bias_g + gate * 256 + nhalf * 128;

    float acc[2][4][4];
    #pragma unroll
    for (int i = 0; i < 2; ++i)
        #pragma unroll
        for (int j = 0; j < 4; ++j)
            #pragma unroll
            for (int q = 0; q < 4; ++q) acc[i][j][q] = 0.f;

    // staging per chunk: A 64 rows x 8 units(16B) = 512 -> 2/thread;
    //                    B 128 rows x 8 units    = 1024 -> 4/thread
#define STAGE(kc, slot) do { \
        _Pragma("unroll") \
        for (int _it = 0; _it < 2; ++_it) { \
            int _u = tid + _it * 256; int _r = _u >> 3; int _c = _u & 7; \
            int _ar = min(bm + _r, Mtot - 1); \
            CP_ASYNC16(sb + (slot) + SM_A + swz8(_r, _c), \
                       A16 + (size_t)_ar * D + (kc) * 64 + _c * 8); \
        } \
        _Pragma("unroll") \
        for (int _it = 0; _it < 4; ++_it) { \
            int _u = tid + _it * 256; int _r = _u >> 3; int _c = _u & 7; \
            CP_ASYNC16(sb + (slot) + SM_B + swz8(_r, _c), \
                       Bt + (size_t)_r * D + (kc) * 64 + _c * 8); \
        } \
    } while (0)

    STAGE(0, 0);
    CP_COMMIT();
    STAGE(1, SM_STAGE);
    CP_COMMIT();

    const int l7  = lane & 7;
    const int l8  = (lane >> 3) & 1;
    const int l16 = lane >> 4;
    const int arow_f = wm * 32 + l8 * 8 + l7;                      // + mf*16
    const int brow   = wn * 32 + (lane & 7) + ((lane >> 4) << 3);  // + nb*16
    const int bch    = (lane >> 3) & 1;

    #pragma unroll 1
    for (int kc = 0; kc < 4; ++kc) {
        CP_WAIT_1();
        __syncthreads();
        if (kc + 2 < 4) {
            uint32_t ns = (uint32_t)(((kc + 2) % 3) * SM_STAGE);
            STAGE(kc + 2, ns);
        }
        CP_COMMIT();

        const uint32_t base = sb + (uint32_t)((kc % 3) * SM_STAGE);
        uint32_t ah[2][4], bb[2][4];
        #pragma unroll
        for (int s = 0; s < 4; ++s) {       // 4 k16 groups in BK=64
            #pragma unroll
            for (int mf = 0; mf < 2; ++mf)
                ldsm_x4(ah[mf], base + SM_A + swz8(arow_f + mf * 16, 2 * s + l16));
            #pragma unroll
            for (int nb = 0; nb < 2; ++nb)
                ldsm_x4(bb[nb], base + SM_B + swz8(brow + nb * 16, 2 * s + bch));
            #pragma unroll
            for (int mf = 0; mf < 2; ++mf)
                #pragma unroll
                for (int nf = 0; nf < 4; ++nf)
                    mma_f16(acc[mf][nf], ah[mf], &bb[nf >> 1][(nf & 1) * 2]);
        }
    }

    // ---- epilogue (direct, latency-parallel global accesses) ----
    float2 bias2[4];
    #pragma unroll
    for (int nf = 0; nf < 4; ++nf)
        bias2[nf] = *(const float2*)(bias + wn * 32 + nf * 8 + 2 * (lane & 3));

    #pragma unroll
    for (int mf = 0; mf < 2; ++mf) {
        #pragma unroll
        for (int half = 0; half < 2; ++half) {
            int r = bm + wm * 32 + mf * 16 + (lane >> 2) + half * 8;
            bool ok = r < Mtot;
            int sid = (MODE == 0 && ok) ? seg[r] : 0;
            #pragma unroll
            for (int nf = 0; nf < 4; ++nf) {
                int cn = nhalf * 128 + wn * 32 + nf * 8 + 2 * (lane & 3);
                float v0 = acc[mf][nf][half * 2 + 0] + bias2[nf].x;
                float v1 = acc[mf][nf][half * 2 + 1] + bias2[nf].y;
                if (!ok) continue;
                size_t o = (size_t)r * D + cn;
                if (MODE == 0) {
                    float2 ccv = *(const float2*)(cc + o);
                    float* dst = fc + (size_t)sid * D + cn;
                    atomicAdd(dst,     sigmoid_f(v0) * ccv.x);
                    atomicAdd(dst + 1, sigmoid_f(v1) * ccv.y);
                } else if (MODE == 1) {
                    float r0, r1;
                    if (gate == 2) { r0 = tanhf(v0); r1 = tanhf(v1); }
                    else           { r0 = sigmoid_f(v0); r1 = sigmoid_f(v1); }
                    float* op = (gate == 0) ? o0 : o2;
                    *(float2*)(op + o) = make_float2(r0, r1);
                } else {
                    // MODE 2: fused LSTM final. v = o-gate pre-activation.
                    float2 iv = *(const float2*)(o0 + o);   // sig(i)
                    float2 gv = *(const float2*)(o2 + o);   // tanh(g)
                    float2 fv = *(const float2*)(fc + o);   // fc
                    float c0 = iv.x * gv.x + fv.x;
                    float c1 = iv.y * gv.y + fv.y;
                    float h0 = sigmoid_f(v0) * tanhf(c0);
                    float h1 = sigmoid_f(v1) * tanhf(c1);
                    *(float2*)(out + o) = make_float2(h0, h1);
                    *(float2*)(out + (size_t)total + o) = make_float2(c0, c1);
                }
            }
        }
    }
#undef STAGE
}

// ---------------------------------------------------------------------------
extern "C" void kernel_launch(void* const* d_in, const int* in_sizes, int n_in,
                              void* d_out, int out_size) {
    const float* child_hs = (const float*)d_in[0];
    const float* child_cs = (const float*)d_in[1];
    const int*   seg      = (const int*)d_in[2];
    const float* Wg = (const float*)d_in[4];
    const float* bg = (const float*)d_in[5];
    const float* Wf = (const float*)d_in[6];
    const float* bf = (const float*)d_in[7];
    (void)n_in;

    int E = in_sizes[2];
    int P = out_size / (2 * D);
    if (P > MAX_P) P = MAX_P;
    if (E > MAX_E) E = MAX_E;

    float* out = (float*)d_out;

    static bool inited = false;
    static float *fc_p, *ia_p, *ga_p;
    static __half *hs16_p, *sum16_p, *wf_p, *wg_p;
    if (!inited) {
        cudaGetSymbolAddress((void**)&fc_p,    g_fc);
        cudaGetSymbolAddress((void**)&ia_p,    g_iact);
        cudaGetSymbolAddress((void**)&ga_p,    g_gact);
        cudaGetSymbolAddress((void**)&hs16_p,  g_hs16);
        cudaGetSymbolAddress((void**)&sum16_p, g_hssum16);
        cudaGetSymbolAddress((void**)&wf_p,    g_wf16);
        cudaGetSymbolAddress((void**)&wg_p,    g_wg16);
        cudaFuncSetAttribute(k_gemm<0>, cudaFuncAttributeMaxDynamicSharedMemorySize, SM_TOTAL);
        cudaFuncSetAttribute(k_gemm<1>, cudaFuncAttributeMaxDynamicSharedMemorySize, SM_TOTAL);
        cudaFuncSetAttribute(k_gemm<2>, cudaFuncAttributeMaxDynamicSharedMemorySize, SM_TOTAL);
        inited = true;
    }

    // weight transpose + fp16 round
    k_wsplit<<<dim3(D / 32, D / 32), 256>>>(Wf, D, wf_p);
    k_wsplit<<<dim3(D3 / 32, D / 32), 256>>>(Wg, D3, wg_p);

    // segment sum (emits fp16 hs_sum, fp16 child_hs, zeroes fc)
    k_hs_sum<<<P, 256>>>(child_hs, seg, E, hs16_p, sum16_p, fc_p);

    // fGEMM: fc[seg[e]] += sigmoid(hs@Wf^T + bf) * cs
    k_gemm<0><<<dim3(2, (E + 63) / 64), 256, SM_TOTAL>>>(
        hs16_p, wf_p, bf, child_cs, seg, fc_p,
        nullptr, nullptr, nullptr, nullptr, 0, E);

    // gates i and g: x bit0 = nhalf, bit1 = gate(0/2)
    k_gemm<1><<<dim3(4, (P + 63) / 64), 256, SM_TOTAL>>>(
        sum16_p, wg_p, bg, nullptr, nullptr, nullptr,
        ia_p, nullptr, ga_p, nullptr, 0, P);

    // gate o + fused LSTM final -> out (h then c)
    k_gemm<2><<<dim3(2, (P + 63) / 64), 256, SM_TOTAL>>>(
        sum16_p, wg_p, bg, nullptr, nullptr, fc_p,
        ia_p, nullptr, ga_p, out, P * D, P);
}

// round 15
// speedup vs baseline: 1.0837x; 1.0837x over previous
#include <cuda_runtime.h>
#include <cuda_fp16.h>
#include <math.h>
#include <stdint.h>

// TreeLSTM — round 15: merged fgemm + interleaved i/g-gates in ONE launch;
// gates write ig = sig(i)*tanh(g) directly (gact buffer deleted).
// GEMM core identical to R13 (CTA 64x128, warp 32x32, 24 warps/SM).
//
//  k_wsplit_f : Wf -> wf16 [256][256]
//  k_wsplit_g : Wg -> wig16 [512][256] (i/g interleaved by 16) + wo16 [256][256]
//  k_hs_sum   : segment sum -> fp16; child_hs -> fp16; zero fc rows
//  k_main     : jobs 0-1: fc[seg[e]] += sig(hs@Wf + bf)*cs   (atomics)
//               jobs 2-5: ig = sig(i)*tanh(g)
//  k_tail     : gate o + fused final: c = ig + fc; h = sig(o)*tanh(c)

#define D    256
#define D3   768
#define MAX_P 100000
#define MAX_E 400000

// ---------------- scratch ----------------
__device__ float g_fc[(size_t)MAX_P * D];
__device__ float g_ig[(size_t)MAX_P * D];
__device__ __half g_hs16[(size_t)MAX_E * D];
__device__ __half g_hssum16[(size_t)MAX_P * D];
__device__ __half g_wf16[D * D];        // W_f^T
__device__ __half g_wig16[2 * D * D];   // i/g interleaved, [512][256]
__device__ __half g_wo16[D * D];        // o gate, [256][256]

// ---------------- helpers ----------------
__device__ __forceinline__ uint32_t smem_to_u32(const void* p) {
    uint32_t a;
    asm("{ .reg .u64 t; cvta.to.shared.u64 t, %1; cvt.u32.u64 %0, t; }" : "=r"(a) : "l"(p));
    return a;
}
__device__ __forceinline__ float sigmoid_f(float x) { return 1.0f / (1.0f + __expf(-x)); }

#define CP_ASYNC16(dst, src) \
    asm volatile("cp.async.cg.shared.global [%0], [%1], 16;" :: "r"(dst), "l"(src))
#define CP_COMMIT() asm volatile("cp.async.commit_group;")
#define CP_WAIT_1() asm volatile("cp.async.wait_group 1;")

__device__ __forceinline__ void ldsm_x4(uint32_t a[4], uint32_t addr) {
    asm volatile("ldmatrix.sync.aligned.m8n8.x4.shared.b16 {%0,%1,%2,%3}, [%4];"
        : "=r"(a[0]), "=r"(a[1]), "=r"(a[2]), "=r"(a[3]) : "r"(addr));
}
__device__ __forceinline__ void mma_f16(float c[4], const uint32_t a[4], const uint32_t b[2]) {
    asm volatile(
        "mma.sync.aligned.m16n8k16.row.col.f32.f16.f16.f32 "
        "{%0,%1,%2,%3}, {%4,%5,%6,%7}, {%8,%9}, {%0,%1,%2,%3};"
        : "+f"(c[0]), "+f"(c[1]), "+f"(c[2]), "+f"(c[3])
        : "r"(a[0]), "r"(a[1]), "r"(a[2]), "r"(a[3]), "r"(b[0]), "r"(b[1]));
}

// Swizzled byte offset in a [rows][64 fp16] tile: 128B rows, 8 chunks of 16B.
__device__ __forceinline__ uint32_t swz8(int row, int ch) {
    return (uint32_t)(row * 128 + (((ch) ^ ((row) & 7)) << 4));
}

// ---------------------------------------------------------------------------
// k_wsplit_f: Wf[256 x 256] -> wf16 [n][k] fp16
// ---------------------------------------------------------------------------
__global__ void k_wsplit_f(const float* __restrict__ W, __half* __restrict__ T) {
    __shared__ float s[32][33];
    int nt = blockIdx.x * 32, kt = blockIdx.y * 32;
    int tx = threadIdx.x & 31, ty = threadIdx.x >> 5;
    #pragma unroll
    for (int i = 0; i < 4; ++i)
        s[ty + i * 8][tx] = W[(size_t)(kt + ty + i * 8) * D + nt + tx];
    __syncthreads();
    #pragma unroll
    for (int i = 0; i < 4; ++i) {
        int n = nt + ty + i * 8;
        int k = kt + tx;
        T[(size_t)n * D + k] = __float2half_rn(s[tx][ty + i * 8]);
    }
}

// ---------------------------------------------------------------------------
// k_wsplit_g: Wg[256 x 768] -> wig16 (i/g interleaved by 16 cols) + wo16.
//   gate 0 col c -> wig row (c>>4)*32 + (c&15)
//   gate 2 col c -> wig row (c>>4)*32 + 16 + (c&15)
//   gate 1 col c -> wo  row c
// ---------------------------------------------------------------------------
__global__ void k_wsplit_g(const float* __restrict__ W,
                           __half* __restrict__ Tig, __half* __restrict__ To) {
    __shared__ float s[32][33];
    int nt = blockIdx.x * 32, kt = blockIdx.y * 32;
    int tx = threadIdx.x & 31, ty = threadIdx.x >> 5;
    #pragma unroll
    for (int i = 0; i < 4; ++i)
        s[ty + i * 8][tx] = W[(size_t)(kt + ty + i * 8) * D3 + nt + tx];
    __syncthreads();
    #pragma unroll
    for (int i = 0; i < 4; ++i) {
        int n = nt + ty + i * 8;
        int k = kt + tx;
        __half h = __float2half_rn(s[tx][ty + i * 8]);
        int gate = n >> 8, c = n & 255;
        if (gate == 0)      Tig[(size_t)((c >> 4) * 32 + (c & 15)) * D + k] = h;
        else if (gate == 2) Tig[(size_t)((c >> 4) * 32 + 16 + (c & 15)) * D + k] = h;
        else                To[(size_t)c * D + k] = h;
    }
}

// ---------------------------------------------------------------------------
// k_hs_sum: segment sum -> fp16; child_hs -> fp16; zero fc rows
// ---------------------------------------------------------------------------
__global__ void k_hs_sum(const float* __restrict__ hs, const int* __restrict__ seg,
                         int E, __half* __restrict__ hs16,
                         __half* __restrict__ sum16, float* __restrict__ fc) {
    __shared__ int sb2[2];
    int p = blockIdx.x;
    if (threadIdx.x < 2) {
        int target = p + (int)threadIdx.x;
        int lo = 0, hi = E;
        while (lo < hi) { int m = (lo + hi) >> 1; if (seg[m] < target) lo = m + 1; else hi = m; }
        sb2[threadIdx.x] = lo;
    }
    fc[(size_t)p * D + threadIdx.x] = 0.0f;
    __syncthreads();
    int lo = sb2[0], hi = sb2[1];
    float s = 0.0f;
    for (int e = lo; e < hi; ++e) {
        float v = hs[(size_t)e * D + threadIdx.x];
        s += v;
        hs16[(size_t)e * D + threadIdx.x] = __float2half_rn(v);
    }
    sum16[(size_t)p * D + threadIdx.x] = __float2half_rn(s);
}

// ---------------------------------------------------------------------------
// GEMM mainloop macro bits shared by k_main / k_tail.
// CTA 64x128, 256 thr, 8 warps (2m x 4n), warp tile 32x32, BK=64, 3-stage.
// ---------------------------------------------------------------------------
#define SM_A    0
#define SM_B    8192
#define SM_STAGE 24576
#define SM_TOTAL (3 * SM_STAGE + 512)

#define GEMM_STAGE(A16, Bt, kc, slot, bm, Mtot) do { \
        _Pragma("unroll") \
        for (int _it = 0; _it < 2; ++_it) { \
            int _u = tid + _it * 256; int _r = _u >> 3; int _c = _u & 7; \
            int _ar = min((bm) + _r, (Mtot) - 1); \
            CP_ASYNC16(sb + (slot) + SM_A + swz8(_r, _c), \
                       (A16) + (size_t)_ar * D + (kc) * 64 + _c * 8); \
        } \
        _Pragma("unroll") \
        for (int _it = 0; _it < 4; ++_it) { \
            int _u = tid + _it * 256; int _r = _u >> 3; int _c = _u & 7; \
            CP_ASYNC16(sb + (slot) + SM_B + swz8(_r, _c), \
                       (Bt) + (size_t)_r * D + (kc) * 64 + _c * 8); \
        } \
    } while (0)

#define GEMM_MAIN(A16, Bt, bm, Mtot) do { \
    GEMM_STAGE(A16, Bt, 0, 0, bm, Mtot); \
    CP_COMMIT(); \
    GEMM_STAGE(A16, Bt, 1, SM_STAGE, bm, Mtot); \
    CP_COMMIT(); \
    _Pragma("unroll 1") \
    for (int kc = 0; kc < 4; ++kc) { \
        CP_WAIT_1(); \
        __syncthreads(); \
        if (kc + 2 < 4) { \
            uint32_t ns = (uint32_t)(((kc + 2) % 3) * SM_STAGE); \
            GEMM_STAGE(A16, Bt, kc + 2, ns, bm, Mtot); \
        } \
        CP_COMMIT(); \
        const uint32_t base = sb + (uint32_t)((kc % 3) * SM_STAGE); \
        uint32_t ah[2][4], bb[2][4]; \
        _Pragma("unroll") \
        for (int s = 0; s < 4; ++s) { \
            _Pragma("unroll") \
            for (int mf = 0; mf < 2; ++mf) \
                ldsm_x4(ah[mf], base + SM_A + swz8(arow_f + mf * 16, 2 * s + l16)); \
            _Pragma("unroll") \
            for (int nb = 0; nb < 2; ++nb) \
                ldsm_x4(bb[nb], base + SM_B + swz8(brow + nb * 16, 2 * s + bch)); \
            _Pragma("unroll") \
            for (int mf = 0; mf < 2; ++mf) \
                _Pragma("unroll") \
                for (int nf = 0; nf < 4; ++nf) \
                    mma_f16(acc[mf][nf], ah[mf], &bb[nf >> 1][(nf & 1) * 2]); \
        } \
    } \
} while (0)

// ---------------------------------------------------------------------------
// k_main: grid (6, 6250).
//   job 0,1: fgemm n-half; A = hs16, M = E. Epilogue: atomic fc.
//   job 2-5: gates-ig tile (interleaved N 512 = 4 tiles); A = sum16, M = P.
//            Epilogue: ig = sig(i)*tanh(g).
// ---------------------------------------------------------------------------
__global__ void __launch_bounds__(256, 3)
k_main(const __half* __restrict__ hs16, const __half* __restrict__ sum16,
       const __half* __restrict__ wf, const __half* __restrict__ wig,
       const float* __restrict__ bf, const float* __restrict__ bg,
       const float* __restrict__ cc, const int* __restrict__ seg,
       float* __restrict__ fc, float* __restrict__ ig,
       int E, int P, int ptiles) {
    const int job = blockIdx.x;
    const bool isf = (job < 2);
    if (!isf && (int)blockIdx.y >= ptiles) return;

    extern __shared__ char smem[];
    const uint32_t sb = smem_to_u32(smem);
    const int tid  = threadIdx.x;
    const int lane = tid & 31;
    const int wid  = tid >> 5;
    const int wm   = wid >> 2;
    const int wn   = wid & 3;
    const int bm   = blockIdx.y * 64;
    const int nsel = isf ? job : (job - 2);

    const __half* A16 = isf ? hs16 : sum16;
    const __half* Bt  = (isf ? wf : wig) + (size_t)nsel * 128 * D;
    const int Mtot    = isf ? E : P;

    float acc[2][4][4];
    #pragma unroll
    for (int i = 0; i < 2; ++i)
        #pragma unroll
        for (int j = 0; j < 4; ++j)
            #pragma unroll
            for (int q = 0; q < 4; ++q) acc[i][j][q] = 0.f;

    const int l7  = lane & 7;
    const int l8  = (lane >> 3) & 1;
    const int l16 = lane >> 4;
    const int arow_f = wm * 32 + l8 * 8 + l7;
    const int brow   = wn * 32 + (lane & 7) + ((lane >> 4) << 3);
    const int bch    = (lane >> 3) & 1;

    GEMM_MAIN(A16, Bt, bm, Mtot);

    // ---- epilogue ----
    if (isf) {
        float2 bias2[4];
        #pragma unroll
        for (int nf = 0; nf < 4; ++nf)
            bias2[nf] = *(const float2*)(bf + nsel * 128 + wn * 32 + nf * 8 + 2 * (lane & 3));
        #pragma unroll
        for (int mf = 0; mf < 2; ++mf) {
            #pragma unroll
            for (int half = 0; half < 2; ++half) {
                int r = bm + wm * 32 + mf * 16 + (lane >> 2) + half * 8;
                if (r >= Mtot) continue;
                int sid = seg[r];
                #pragma unroll
                for (int nf = 0; nf < 4; ++nf) {
                    int cn = nsel * 128 + wn * 32 + nf * 8 + 2 * (lane & 3);
                    float v0 = acc[mf][nf][half * 2 + 0] + bias2[nf].x;
                    float v1 = acc[mf][nf][half * 2 + 1] + bias2[nf].y;
                    size_t o = (size_t)r * D + cn;
                    float2 ccv = *(const float2*)(cc + o);
                    float* dst = fc + (size_t)sid * D + cn;
                    atomicAdd(dst,     sigmoid_f(v0) * ccv.x);
                    atomicAdd(dst + 1, sigmoid_f(v1) * ccv.y);
                }
            }
        }
    } else {
        // interleaved: orig col oc = (nsel*4 + wn)*16 + nf*8 + 2*(lane&3), nf 0..1
        // acc[mf][nf] = i-gate, acc[mf][nf+2] = g-gate for the same oc.
        int ocbase = (nsel * 4 + wn) * 16 + 2 * (lane & 3);
        float2 bi[2], bgv[2];
        #pragma unroll
        for (int nf = 0; nf < 2; ++nf) {
            bi[nf]  = *(const float2*)(bg + ocbase + nf * 8);
            bgv[nf] = *(const float2*)(bg + 512 + ocbase + nf * 8);
        }
        #pragma unroll
        for (int mf = 0; mf < 2; ++mf) {
            #pragma unroll
            for (int half = 0; half < 2; ++half) {
                int r = bm + wm * 32 + mf * 16 + (lane >> 2) + half * 8;
                if (r >= Mtot) continue;
                #pragma unroll
                for (int nf = 0; nf < 2; ++nf) {
                    int oc = ocbase + nf * 8;
                    float i0 = sigmoid_f(acc[mf][nf][half * 2 + 0] + bi[nf].x);
                    float i1 = sigmoid_f(acc[mf][nf][half * 2 + 1] + bi[nf].y);
                    float g0 = tanhf(acc[mf][nf + 2][half * 2 + 0] + bgv[nf].x);
                    float g1 = tanhf(acc[mf][nf + 2][half * 2 + 1] + bgv[nf].y);
                    *(float2*)(ig + (size_t)r * D + oc) = make_float2(i0 * g0, i1 * g1);
                }
            }
        }
    }
}

// ---------------------------------------------------------------------------
// k_tail: gate o + fused LSTM final. grid (2, ptiles).
//   c = ig + fc; h = sig(o)*tanh(c); out = [h | c]
// ---------------------------------------------------------------------------
__global__ void __launch_bounds__(256, 3)
k_tail(const __half* __restrict__ sum16, const __half* __restrict__ wo,
       const float* __restrict__ bg,
       const float* __restrict__ ig, const float* __restrict__ fc,
       float* __restrict__ out, int total, int P) {
    extern __shared__ char smem[];
    const uint32_t sb = smem_to_u32(smem);
    const int tid  = threadIdx.x;
    const int lane = tid & 31;
    const int wid  = tid >> 5;
    const int wm   = wid >> 2;
    const int wn   = wid & 3;
    const int bm   = blockIdx.y * 64;
    const int nhalf = blockIdx.x;

    const __half* Bt = wo + (size_t)nhalf * 128 * D;
    const float* bias = bg + 256 + nhalf * 128;
    const int Mtot = P;

    float acc[2][4][4];
    #pragma unroll
    for (int i = 0; i < 2; ++i)
        #pragma unroll
        for (int j = 0; j < 4; ++j)
            #pragma unroll
            for (int q = 0; q < 4; ++q) acc[i][j][q] = 0.f;

    const int l7  = lane & 7;
    const int l8  = (lane >> 3) & 1;
    const int l16 = lane >> 4;
    const int arow_f = wm * 32 + l8 * 8 + l7;
    const int brow   = wn * 32 + (lane & 7) + ((lane >> 4) << 3);
    const int bch    = (lane >> 3) & 1;

    GEMM_MAIN(sum16, Bt, bm, Mtot);

    float2 bias2[4];
    #pragma unroll
    for (int nf = 0; nf < 4; ++nf)
        bias2[nf] = *(const float2*)(bias + wn * 32 + nf * 8 + 2 * (lane & 3));

    #pragma unroll
    for (int mf = 0; mf < 2; ++mf) {
        #pragma unroll
        for (int half = 0; half < 2; ++half) {
            int r = bm + wm * 32 + mf * 16 + (lane >> 2) + half * 8;
            if (r >= Mtot) continue;
            #pragma unroll
            for (int nf = 0; nf < 4; ++nf) {
                int cn = nhalf * 128 + wn * 32 + nf * 8 + 2 * (lane & 3);
                float v0 = acc[mf][nf][half * 2 + 0] + bias2[nf].x;
                float v1 = acc[mf][nf][half * 2 + 1] + bias2[nf].y;
                size_t o = (size_t)r * D + cn;
                float2 igv = *(const float2*)(ig + o);
                float2 fv  = *(const float2*)(fc + o);
                float c0 = igv.x + fv.x;
                float c1 = igv.y + fv.y;
                float h0 = sigmoid_f(v0) * tanhf(c0);
                float h1 = sigmoid_f(v1) * tanhf(c1);
                *(float2*)(out + o) = make_float2(h0, h1);
                *(float2*)(out + (size_t)total + o) = make_float2(c0, c1);
            }
        }
    }
}

// ---------------------------------------------------------------------------
extern "C" void kernel_launch(void* const* d_in, const int* in_sizes, int n_in,
                              void* d_out, int out_size) {
    const float* child_hs = (const float*)d_in[0];
    const float* child_cs = (const float*)d_in[1];
    const int*   seg      = (const int*)d_in[2];
    const float* Wg = (const float*)d_in[4];
    const float* bg = (const float*)d_in[5];
    const float* Wf = (const float*)d_in[6];
    const float* bf = (const float*)d_in[7];
    (void)n_in;

    int E = in_sizes[2];
    int P = out_size / (2 * D);
    if (P > MAX_P) P = MAX_P;
    if (E > MAX_E) E = MAX_E;

    float* out = (float*)d_out;

    static bool inited = false;
    static float *fc_p, *ig_p;
    static __half *hs16_p, *sum16_p, *wf_p, *wig_p, *wo_p;
    if (!inited) {
        cudaGetSymbolAddress((void**)&fc_p,    g_fc);
        cudaGetSymbolAddress((void**)&ig_p,    g_ig);
        cudaGetSymbolAddress((void**)&hs16_p,  g_hs16);
        cudaGetSymbolAddress((void**)&sum16_p, g_hssum16);
        cudaGetSymbolAddress((void**)&wf_p,    g_wf16);
        cudaGetSymbolAddress((void**)&wig_p,   g_wig16);
        cudaGetSymbolAddress((void**)&wo_p,    g_wo16);
        cudaFuncSetAttribute(k_main, cudaFuncAttributeMaxDynamicSharedMemorySize, SM_TOTAL);
        cudaFuncSetAttribute(k_tail, cudaFuncAttributeMaxDynamicSharedMemorySize, SM_TOTAL);
        inited = true;
    }

    int etiles = (E + 63) / 64;
    int ptiles = (P + 63) / 64;

    // weight prep
    k_wsplit_f<<<dim3(D / 32, D / 32), 256>>>(Wf, wf_p);
    k_wsplit_g<<<dim3(D3 / 32, D / 32), 256>>>(Wg, wig_p, wo_p);

    // segment sum (emits fp16 hs_sum, fp16 child_hs, zeroes fc)
    k_hs_sum<<<P, 256>>>(child_hs, seg, E, hs16_p, sum16_p, fc_p);

    // merged fgemm + ig gates
    k_main<<<dim3(6, etiles), 256, SM_TOTAL>>>(
        hs16_p, sum16_p, wf_p, wig_p, bf, bg, child_cs, seg,
        fc_p, ig_p, E, P, ptiles);

    // gate o + fused final
    k_tail<<<dim3(2, ptiles), 256, SM_TOTAL>>>(
        sum16_p, wo_p, bg, ig_p, fc_p, out, P * D, P);
}

// round 16
// speedup vs baseline: 1.3886x; 1.2813x over previous
#include <cuda_runtime.h>
#include <cuda_fp16.h>
#include <math.h>
#include <stdint.h>

// TreeLSTM — round 16: all three GEMMs co-scheduled in ONE k_main launch
// (jobs: 0-1 fgemm | 2-5 ig-gates | 6-7 o-gate); elementwise tail;
// hs_sum amortized 8 parents/CTA. GEMM core = R13 (64x128, 24 warps/SM).

#define D    256
#define D3   768
#define MAX_P 100000
#define MAX_E 400000

// ---------------- scratch ----------------
__device__ float g_fc[(size_t)MAX_P * D];
__device__ float g_ig[(size_t)MAX_P * D];
__device__ float g_oact[(size_t)MAX_P * D];
__device__ __half g_hs16[(size_t)MAX_E * D];
__device__ __half g_hssum16[(size_t)MAX_P * D];
__device__ __half g_wf16[D * D];        // W_f^T
__device__ __half g_wig16[2 * D * D];   // i/g interleaved, [512][256]
__device__ __half g_wo16[D * D];        // o gate, [256][256]

// ---------------- helpers ----------------
__device__ __forceinline__ uint32_t smem_to_u32(const void* p) {
    uint32_t a;
    asm("{ .reg .u64 t; cvta.to.shared.u64 t, %1; cvt.u32.u64 %0, t; }" : "=r"(a) : "l"(p));
    return a;
}
__device__ __forceinline__ float sigmoid_f(float x) { return 1.0f / (1.0f + __expf(-x)); }

#define CP_ASYNC16(dst, src) \
    asm volatile("cp.async.cg.shared.global [%0], [%1], 16;" :: "r"(dst), "l"(src))
#define CP_COMMIT() asm volatile("cp.async.commit_group;")
#define CP_WAIT_1() asm volatile("cp.async.wait_group 1;")

__device__ __forceinline__ void ldsm_x4(uint32_t a[4], uint32_t addr) {
    asm volatile("ldmatrix.sync.aligned.m8n8.x4.shared.b16 {%0,%1,%2,%3}, [%4];"
        : "=r"(a[0]), "=r"(a[1]), "=r"(a[2]), "=r"(a[3]) : "r"(addr));
}
__device__ __forceinline__ void mma_f16(float c[4], const uint32_t a[4], const uint32_t b[2]) {
    asm volatile(
        "mma.sync.aligned.m16n8k16.row.col.f32.f16.f16.f32 "
        "{%0,%1,%2,%3}, {%4,%5,%6,%7}, {%8,%9}, {%0,%1,%2,%3};"
        : "+f"(c[0]), "+f"(c[1]), "+f"(c[2]), "+f"(c[3])
        : "r"(a[0]), "r"(a[1]), "r"(a[2]), "r"(a[3]), "r"(b[0]), "r"(b[1]));
}

// Swizzled byte offset in a [rows][64 fp16] tile: 128B rows, 8 chunks of 16B.
__device__ __forceinline__ uint32_t swz8(int row, int ch) {
    return (uint32_t)(row * 128 + (((ch) ^ ((row) & 7)) << 4));
}

// ---------------------------------------------------------------------------
// k_wsplit_f: Wf[256 x 256] -> wf16 [n][k] fp16
// ---------------------------------------------------------------------------
__global__ void k_wsplit_f(const float* __restrict__ W, __half* __restrict__ T) {
    __shared__ float s[32][33];
    int nt = blockIdx.x * 32, kt = blockIdx.y * 32;
    int tx = threadIdx.x & 31, ty = threadIdx.x >> 5;
    #pragma unroll
    for (int i = 0; i < 4; ++i)
        s[ty + i * 8][tx] = W[(size_t)(kt + ty + i * 8) * D + nt + tx];
    __syncthreads();
    #pragma unroll
    for (int i = 0; i < 4; ++i) {
        int n = nt + ty + i * 8;
        int k = kt + tx;
        T[(size_t)n * D + k] = __float2half_rn(s[tx][ty + i * 8]);
    }
}

// ---------------------------------------------------------------------------
// k_wsplit_g: Wg[256 x 768] -> wig16 (i/g interleaved by 16 cols) + wo16.
// ---------------------------------------------------------------------------
__global__ void k_wsplit_g(const float* __restrict__ W,
                           __half* __restrict__ Tig, __half* __restrict__ To) {
    __shared__ float s[32][33];
    int nt = blockIdx.x * 32, kt = blockIdx.y * 32;
    int tx = threadIdx.x & 31, ty = threadIdx.x >> 5;
    #pragma unroll
    for (int i = 0; i < 4; ++i)
        s[ty + i * 8][tx] = W[(size_t)(kt + ty + i * 8) * D3 + nt + tx];
    __syncthreads();
    #pragma unroll
    for (int i = 0; i < 4; ++i) {
        int n = nt + ty + i * 8;
        int k = kt + tx;
        __half h = __float2half_rn(s[tx][ty + i * 8]);
        int gate = n >> 8, c = n & 255;
        if (gate == 0)      Tig[(size_t)((c >> 4) * 32 + (c & 15)) * D + k] = h;
        else if (gate == 2) Tig[(size_t)((c >> 4) * 32 + 16 + (c & 15)) * D + k] = h;
        else                To[(size_t)c * D + k] = h;
    }
}

// ---------------------------------------------------------------------------
// k_hs_sum: 8 parents per CTA. Segment sums -> fp16; child_hs -> fp16;
// zero fc rows. 9 boundary searches amortized over 8 parents.
// ---------------------------------------------------------------------------
__global__ void k_hs_sum(const float* __restrict__ hs, const int* __restrict__ seg,
                         int E, int P, __half* __restrict__ hs16,
                         __half* __restrict__ sum16, float* __restrict__ fc) {
    __shared__ int sb[9];
    int p0 = blockIdx.x * 8;
    if (threadIdx.x < 9) {
        int target = p0 + (int)threadIdx.x;
        int lo = 0, hi = E;
        while (lo < hi) { int m = (lo + hi) >> 1; if (seg[m] < target) lo = m + 1; else hi = m; }
        sb[threadIdx.x] = lo;
    }
    __syncthreads();
    #pragma unroll 1
    for (int j = 0; j < 8; ++j) {
        int p = p0 + j;
        if (p >= P) break;
        fc[(size_t)p * D + threadIdx.x] = 0.0f;
        float s = 0.0f;
        int lo = sb[j], hi = sb[j + 1];
        for (int e = lo; e < hi; ++e) {
            float v = hs[(size_t)e * D + threadIdx.x];
            s += v;
            hs16[(size_t)e * D + threadIdx.x] = __float2half_rn(v);
        }
        sum16[(size_t)p * D + threadIdx.x] = __float2half_rn(s);
    }
}

// ---------------------------------------------------------------------------
// GEMM mainloop macro bits. CTA 64x128, 256 thr, 8 warps (2m x 4n),
// warp tile 32x32, BK=64, 3-stage cp.async.
// ---------------------------------------------------------------------------
#define SM_A    0
#define SM_B    8192
#define SM_STAGE 24576
#define SM_TOTAL (3 * SM_STAGE + 512)

#define GEMM_STAGE(A16, Bt, kc, slot, bm, Mtot) do { \
        _Pragma("unroll") \
        for (int _it = 0; _it < 2; ++_it) { \
            int _u = tid + _it * 256; int _r = _u >> 3; int _c = _u & 7; \
            int _ar = min((bm) + _r, (Mtot) - 1); \
            CP_ASYNC16(sb + (slot) + SM_A + swz8(_r, _c), \
                       (A16) + (size_t)_ar * D + (kc) * 64 + _c * 8); \
        } \
        _Pragma("unroll") \
        for (int _it = 0; _it < 4; ++_it) { \
            int _u = tid + _it * 256; int _r = _u >> 3; int _c = _u & 7; \
            CP_ASYNC16(sb + (slot) + SM_B + swz8(_r, _c), \
                       (Bt) + (size_t)_r * D + (kc) * 64 + _c * 8); \
        } \
    } while (0)

#define GEMM_MAIN(A16, Bt, bm, Mtot) do { \
    GEMM_STAGE(A16, Bt, 0, 0, bm, Mtot); \
    CP_COMMIT(); \
    GEMM_STAGE(A16, Bt, 1, SM_STAGE, bm, Mtot); \
    CP_COMMIT(); \
    _Pragma("unroll 1") \
    for (int kc = 0; kc < 4; ++kc) { \
        CP_WAIT_1(); \
        __syncthreads(); \
        if (kc + 2 < 4) { \
            uint32_t ns = (uint32_t)(((kc + 2) % 3) * SM_STAGE); \
            GEMM_STAGE(A16, Bt, kc + 2, ns, bm, Mtot); \
        } \
        CP_COMMIT(); \
        const uint32_t base = sb + (uint32_t)((kc % 3) * SM_STAGE); \
        uint32_t ah[2][4], bb[2][4]; \
        _Pragma("unroll") \
        for (int s = 0; s < 4; ++s) { \
            _Pragma("unroll") \
            for (int mf = 0; mf < 2; ++mf) \
                ldsm_x4(ah[mf], base + SM_A + swz8(arow_f + mf * 16, 2 * s + l16)); \
            _Pragma("unroll") \
            for (int nb = 0; nb < 2; ++nb) \
                ldsm_x4(bb[nb], base + SM_B + swz8(brow + nb * 16, 2 * s + bch)); \
            _Pragma("unroll") \
            for (int mf = 0; mf < 2; ++mf) \
                _Pragma("unroll") \
                for (int nf = 0; nf < 4; ++nf) \
                    mma_f16(acc[mf][nf], ah[mf], &bb[nf >> 1][(nf & 1) * 2]); \
        } \
    } \
} while (0)

// ---------------------------------------------------------------------------
// k_main: grid (8, etiles).
//   job 0,1: fgemm n-half; A = hs16, M = E. Epilogue: atomic fc.
//   job 2-5: gates-ig tile; A = sum16, M = P. Epilogue: ig = sig(i)*tanh(g).
//   job 6,7: o-gate n-half; A = sum16, M = P. Epilogue: oact = sig(o+b).
// ---------------------------------------------------------------------------
__global__ void __launch_bounds__(256, 3)
k_main(const __half* __restrict__ hs16, const __half* __restrict__ sum16,
       const __half* __restrict__ wf, const __half* __restrict__ wig,
       const __half* __restrict__ wo,
       const float* __restrict__ bf, const float* __restrict__ bg,
       const float* __restrict__ cc, const int* __restrict__ seg,
       float* __restrict__ fc, float* __restrict__ ig, float* __restrict__ oact,
       int E, int P, int ptiles) {
    const int job = blockIdx.x;
    const int kind = (job < 2) ? 0 : (job < 6 ? 1 : 2);
    if (kind != 0 && (int)blockIdx.y >= ptiles) return;

    extern __shared__ char smem[];
    const uint32_t sb = smem_to_u32(smem);
    const int tid  = threadIdx.x;
    const int lane = tid & 31;
    const int wid  = tid >> 5;
    const int wm   = wid >> 2;
    const int wn   = wid & 3;
    const int bm   = blockIdx.y * 64;
    const int nsel = (kind == 0) ? job : (kind == 1 ? job - 2 : job - 6);

    const __half* A16 = (kind == 0) ? hs16 : sum16;
    const __half* Bt  = ((kind == 0) ? wf : (kind == 1 ? wig : wo))
                        + (size_t)nsel * 128 * D;
    const int Mtot    = (kind == 0) ? E : P;

    float acc[2][4][4];
    #pragma unroll
    for (int i = 0; i < 2; ++i)
        #pragma unroll
        for (int j = 0; j < 4; ++j)
            #pragma unroll
            for (int q = 0; q < 4; ++q) acc[i][j][q] = 0.f;

    const int l7  = lane & 7;
    const int l8  = (lane >> 3) & 1;
    const int l16 = lane >> 4;
    const int arow_f = wm * 32 + l8 * 8 + l7;
    const int brow   = wn * 32 + (lane & 7) + ((lane >> 4) << 3);
    const int bch    = (lane >> 3) & 1;

    GEMM_MAIN(A16, Bt, bm, Mtot);

    // ---- epilogue ----
    if (kind == 0) {
        float2 bias2[4];
        #pragma unroll
        for (int nf = 0; nf < 4; ++nf)
            bias2[nf] = *(const float2*)(bf + nsel * 128 + wn * 32 + nf * 8 + 2 * (lane & 3));
        #pragma unroll
        for (int mf = 0; mf < 2; ++mf) {
            #pragma unroll
            for (int half = 0; half < 2; ++half) {
                int r = bm + wm * 32 + mf * 16 + (lane >> 2) + half * 8;
                if (r >= Mtot) continue;
                int sid = seg[r];
                #pragma unroll
                for (int nf = 0; nf < 4; ++nf) {
                    int cn = nsel * 128 + wn * 32 + nf * 8 + 2 * (lane & 3);
                    float v0 = acc[mf][nf][half * 2 + 0] + bias2[nf].x;
                    float v1 = acc[mf][nf][half * 2 + 1] + bias2[nf].y;
                    size_t o = (size_t)r * D + cn;
                    float2 ccv = *(const float2*)(cc + o);
                    float* dst = fc + (size_t)sid * D + cn;
                    atomicAdd(dst,     sigmoid_f(v0) * ccv.x);
                    atomicAdd(dst + 1, sigmoid_f(v1) * ccv.y);
                }
            }
        }
    } else if (kind == 1) {
        int ocbase = (nsel * 4 + wn) * 16 + 2 * (lane & 3);
        float2 bi[2], bgv[2];
        #pragma unroll
        for (int nf = 0; nf < 2; ++nf) {
            bi[nf]  = *(const float2*)(bg + ocbase + nf * 8);
            bgv[nf] = *(const float2*)(bg + 512 + ocbase + nf * 8);
        }
        #pragma unroll
        for (int mf = 0; mf < 2; ++mf) {
            #pragma unroll
            for (int half = 0; half < 2; ++half) {
                int r = bm + wm * 32 + mf * 16 + (lane >> 2) + half * 8;
                if (r >= Mtot) continue;
                #pragma unroll
                for (int nf = 0; nf < 2; ++nf) {
                    int oc = ocbase + nf * 8;
                    float i0 = sigmoid_f(acc[mf][nf][half * 2 + 0] + bi[nf].x);
                    float i1 = sigmoid_f(acc[mf][nf][half * 2 + 1] + bi[nf].y);
                    float g0 = tanhf(acc[mf][nf + 2][half * 2 + 0] + bgv[nf].x);
                    float g1 = tanhf(acc[mf][nf + 2][half * 2 + 1] + bgv[nf].y);
                    *(float2*)(ig + (size_t)r * D + oc) = make_float2(i0 * g0, i1 * g1);
                }
            }
        }
    } else {
        float2 bias2[4];
        #pragma unroll
        for (int nf = 0; nf < 4; ++nf)
            bias2[nf] = *(const float2*)(bg + 256 + nsel * 128 + wn * 32 + nf * 8 + 2 * (lane & 3));
        #pragma unroll
        for (int mf = 0; mf < 2; ++mf) {
            #pragma unroll
            for (int half = 0; half < 2; ++half) {
                int r = bm + wm * 32 + mf * 16 + (lane >> 2) + half * 8;
                if (r >= Mtot) continue;
                #pragma unroll
                for (int nf = 0; nf < 4; ++nf) {
                    int cn = nsel * 128 + wn * 32 + nf * 8 + 2 * (lane & 3);
                    float v0 = acc[mf][nf][half * 2 + 0] + bias2[nf].x;
                    float v1 = acc[mf][nf][half * 2 + 1] + bias2[nf].y;
                    *(float2*)(oact + (size_t)r * D + cn) =
                        make_float2(sigmoid_f(v0), sigmoid_f(v1));
                }
            }
        }
    }
}

// ---------------------------------------------------------------------------
// k_elem: c = ig + fc; h = oact * tanh(c)  (elementwise, float4)
// ---------------------------------------------------------------------------
__global__ void k_elem(const float* __restrict__ oact, const float* __restrict__ ig,
                       const float* __restrict__ fc, float* __restrict__ out,
                       int total) {
    int i4 = blockIdx.x * blockDim.x + threadIdx.x;
    if (i4 * 4 < total) {
        size_t idx = (size_t)i4 * 4;
        float4 ov = *(const float4*)(oact + idx);
        float4 gv = *(const float4*)(ig + idx);
        float4 fv = *(const float4*)(fc + idx);
        float4 c = make_float4(gv.x + fv.x, gv.y + fv.y, gv.z + fv.z, gv.w + fv.w);
        float4 h = make_float4(ov.x * tanhf(c.x), ov.y * tanhf(c.y),
                               ov.z * tanhf(c.z), ov.w * tanhf(c.w));
        *(float4*)(out + idx) = h;
        *(float4*)(out + (size_t)total + idx) = c;
    }
}

// ---------------------------------------------------------------------------
extern "C" void kernel_launch(void* const* d_in, const int* in_sizes, int n_in,
                              void* d_out, int out_size) {
    const float* child_hs = (const float*)d_in[0];
    const float* child_cs = (const float*)d_in[1];
    const int*   seg      = (const int*)d_in[2];
    const float* Wg = (const float*)d_in[4];
    const float* bg = (const float*)d_in[5];
    const float* Wf = (const float*)d_in[6];
    const float* bf = (const float*)d_in[7];
    (void)n_in;

    int E = in_sizes[2];
    int P = out_size / (2 * D);
    if (P > MAX_P) P = MAX_P;
    if (E > MAX_E) E = MAX_E;

    float* out = (float*)d_out;

    static bool inited = false;
    static float *fc_p, *ig_p, *oa_p;
    static __half *hs16_p, *sum16_p, *wf_p, *wig_p, *wo_p;
    if (!inited) {
        cudaGetSymbolAddress((void**)&fc_p,    g_fc);
        cudaGetSymbolAddress((void**)&ig_p,    g_ig);
        cudaGetSymbolAddress((void**)&oa_p,    g_oact);
        cudaGetSymbolAddress((void**)&hs16_p,  g_hs16);
        cudaGetSymbolAddress((void**)&sum16_p, g_hssum16);
        cudaGetSymbolAddress((void**)&wf_p,    g_wf16);
        cudaGetSymbolAddress((void**)&wig_p,   g_wig16);
        cudaGetSymbolAddress((void**)&wo_p,    g_wo16);
        cudaFuncSetAttribute(k_main, cudaFuncAttributeMaxDynamicSharedMemorySize, SM_TOTAL);
        inited = true;
    }

    int etiles = (E + 63) / 64;
    int ptiles = (P + 63) / 64;

    // weight prep
    k_wsplit_f<<<dim3(D / 32, D / 32), 256>>>(Wf, wf_p);
    k_wsplit_g<<<dim3(D3 / 32, D / 32), 256>>>(Wg, wig_p, wo_p);

    // segment sum (8 parents/CTA; emits fp16 buffers, zeroes fc)
    k_hs_sum<<<(P + 7) / 8, 256>>>(child_hs, seg, E, P, hs16_p, sum16_p, fc_p);

    // all three GEMMs co-scheduled
    k_main<<<dim3(8, etiles), 256, SM_TOTAL>>>(
        hs16_p, sum16_p, wf_p, wig_p, wo_p, bf, bg, child_cs, seg,
        fc_p, ig_p, oa_p, E, P, ptiles);

    // elementwise final combine
    k_elem<<<(P * D / 4 + 255) / 256, 256>>>(oa_p, ig_p, fc_p, out, P * D);
}

// round 17
// speedup vs baseline: 1.4504x; 1.0445x over previous
#include <cuda_runtime.h>
#include <cuda_fp16.h>
#include <math.h>
#include <stdint.h>

// TreeLSTM — round 17: R16 + (1) single co-scheduled prep launch (wsplit_f +
// wsplit_g + hs_sum@16 parents/CTA), (2) exact proportionally-interleaved
// flat grid for k_main (no empty CTAs, uniform job mix in every wave),
// (3) fp16 ig/oact intermediates. GEMM core unchanged (64x128, 24 warps/SM).

#define D    256
#define D3   768
#define MAX_P 100000
#define MAX_E 400000

// ---------------- scratch ----------------
__device__ float g_fc[(size_t)MAX_P * D];
__device__ __half g_ig[(size_t)MAX_P * D];
__device__ __half g_oact[(size_t)MAX_P * D];
__device__ __half g_hs16[(size_t)MAX_E * D];
__device__ __half g_hssum16[(size_t)MAX_P * D];
__device__ __half g_wf16[D * D];        // W_f^T
__device__ __half g_wig16[2 * D * D];   // i/g interleaved, [512][256]
__device__ __half g_wo16[D * D];        // o gate, [256][256]

// ---------------- helpers ----------------
__device__ __forceinline__ uint32_t smem_to_u32(const void* p) {
    uint32_t a;
    asm("{ .reg .u64 t; cvta.to.shared.u64 t, %1; cvt.u32.u64 %0, t; }" : "=r"(a) : "l"(p));
    return a;
}
__device__ __forceinline__ float sigmoid_f(float x) { return 1.0f / (1.0f + __expf(-x)); }

#define CP_ASYNC16(dst, src) \
    asm volatile("cp.async.cg.shared.global [%0], [%1], 16;" :: "r"(dst), "l"(src))
#define CP_COMMIT() asm volatile("cp.async.commit_group;")
#define CP_WAIT_1() asm volatile("cp.async.wait_group 1;")

__device__ __forceinline__ void ldsm_x4(uint32_t a[4], uint32_t addr) {
    asm volatile("ldmatrix.sync.aligned.m8n8.x4.shared.b16 {%0,%1,%2,%3}, [%4];"
        : "=r"(a[0]), "=r"(a[1]), "=r"(a[2]), "=r"(a[3]) : "r"(addr));
}
__device__ __forceinline__ void mma_f16(float c[4], const uint32_t a[4], const uint32_t b[2]) {
    asm volatile(
        "mma.sync.aligned.m16n8k16.row.col.f32.f16.f16.f32 "
        "{%0,%1,%2,%3}, {%4,%5,%6,%7}, {%8,%9}, {%0,%1,%2,%3};"
        : "+f"(c[0]), "+f"(c[1]), "+f"(c[2]), "+f"(c[3])
        : "r"(a[0]), "r"(a[1]), "r"(a[2]), "r"(a[3]), "r"(b[0]), "r"(b[1]));
}

// Swizzled byte offset in a [rows][64 fp16] tile: 128B rows, 8 chunks of 16B.
__device__ __forceinline__ uint32_t swz8(int row, int ch) {
    return (uint32_t)(row * 128 + (((ch) ^ ((row) & 7)) << 4));
}

// ---------------------------------------------------------------------------
// k_prep: flat grid, three job kinds co-scheduled.
//   i < 64         : Wf transpose tile (8 x 8 of 32x32)
//   i < 64 + 192   : Wg transpose tile (24 x 8), gate-interleaved scatter
//   else           : hs_sum, 16 parents per CTA (p0 = (i - 256) * 16)
// ---------------------------------------------------------------------------
__global__ void k_prep(const float* __restrict__ Wf, const float* __restrict__ Wg,
                       const float* __restrict__ hs, const int* __restrict__ seg,
                       int E, int P,
                       __half* __restrict__ wf16, __half* __restrict__ wig16,
                       __half* __restrict__ wo16,
                       __half* __restrict__ hs16, __half* __restrict__ sum16,
                       float* __restrict__ fc) {
    __shared__ float s[32][33];
    __shared__ int sb[17];
    const int i = blockIdx.x;
    const int tid = threadIdx.x;

    if (i < 64) {
        // Wf tile
        int nt = (i & 7) * 32, kt = (i >> 3) * 32;
        int tx = tid & 31, ty = tid >> 5;
        #pragma unroll
        for (int q = 0; q < 4; ++q)
            s[ty + q * 8][tx] = Wf[(size_t)(kt + ty + q * 8) * D + nt + tx];
        __syncthreads();
        #pragma unroll
        for (int q = 0; q < 4; ++q) {
            int n = nt + ty + q * 8;
            int k = kt + tx;
            wf16[(size_t)n * D + k] = __float2half_rn(s[tx][ty + q * 8]);
        }
    } else if (i < 256) {
        // Wg tile (gate-interleaved scatter)
        int j = i - 64;
        int nt = (j % 24) * 32, kt = (j / 24) * 32;
        int tx = tid & 31, ty = tid >> 5;
        #pragma unroll
        for (int q = 0; q < 4; ++q)
            s[ty + q * 8][tx] = Wg[(size_t)(kt + ty + q * 8) * D3 + nt + tx];
        __syncthreads();
        #pragma unroll
        for (int q = 0; q < 4; ++q) {
            int n = nt + ty + q * 8;
            int k = kt + tx;
            __half h = __float2half_rn(s[tx][ty + q * 8]);
            int gate = n >> 8, c = n & 255;
            if (gate == 0)      wig16[(size_t)((c >> 4) * 32 + (c & 15)) * D + k] = h;
            else if (gate == 2) wig16[(size_t)((c >> 4) * 32 + 16 + (c & 15)) * D + k] = h;
            else                wo16[(size_t)c * D + k] = h;
        }
    } else {
        // hs_sum: 16 parents per CTA
        int p0 = (i - 256) * 16;
        if (tid < 17) {
            int target = p0 + tid;
            int lo = 0, hi = E;
            while (lo < hi) { int m = (lo + hi) >> 1; if (seg[m] < target) lo = m + 1; else hi = m; }
            sb[tid] = lo;
        }
        __syncthreads();
        #pragma unroll 1
        for (int j = 0; j < 16; ++j) {
            int p = p0 + j;
            if (p >= P) break;
            fc[(size_t)p * D + tid] = 0.0f;
            float sum = 0.0f;
            int lo = sb[j], hi = sb[j + 1];
            for (int e = lo; e < hi; ++e) {
                float v = hs[(size_t)e * D + tid];
                sum += v;
                hs16[(size_t)e * D + tid] = __float2half_rn(v);
            }
            sum16[(size_t)p * D + tid] = __float2half_rn(sum);
        }
    }
}

// ---------------------------------------------------------------------------
// GEMM mainloop macro bits. CTA 64x128, 256 thr, 8 warps (2m x 4n),
// warp tile 32x32, BK=64, 3-stage cp.async.
// ---------------------------------------------------------------------------
#define SM_A    0
#define SM_B    8192
#define SM_STAGE 24576
#define SM_TOTAL (3 * SM_STAGE + 512)

#define GEMM_STAGE(A16, Bt, kc, slot, bm, Mtot) do { \
        _Pragma("unroll") \
        for (int _it = 0; _it < 2; ++_it) { \
            int _u = tid + _it * 256; int _r = _u >> 3; int _c = _u & 7; \
            int _ar = min((bm) + _r, (Mtot) - 1); \
            CP_ASYNC16(sb + (slot) + SM_A + swz8(_r, _c), \
                       (A16) + (size_t)_ar * D + (kc) * 64 + _c * 8); \
        } \
        _Pragma("unroll") \
        for (int _it = 0; _it < 4; ++_it) { \
            int _u = tid + _it * 256; int _r = _u >> 3; int _c = _u & 7; \
            CP_ASYNC16(sb + (slot) + SM_B + swz8(_r, _c), \
                       (Bt) + (size_t)_r * D + (kc) * 64 + _c * 8); \
        } \
    } while (0)

#define GEMM_MAIN(A16, Bt, bm, Mtot) do { \
    GEMM_STAGE(A16, Bt, 0, 0, bm, Mtot); \
    CP_COMMIT(); \
    GEMM_STAGE(A16, Bt, 1, SM_STAGE, bm, Mtot); \
    CP_COMMIT(); \
    _Pragma("unroll 1") \
    for (int kc = 0; kc < 4; ++kc) { \
        CP_WAIT_1(); \
        __syncthreads(); \
        if (kc + 2 < 4) { \
            uint32_t ns = (uint32_t)(((kc + 2) % 3) * SM_STAGE); \
            GEMM_STAGE(A16, Bt, kc + 2, ns, bm, Mtot); \
        } \
        CP_COMMIT(); \
        const uint32_t base = sb + (uint32_t)((kc % 3) * SM_STAGE); \
        uint32_t ah[2][4], bb[2][4]; \
        _Pragma("unroll") \
        for (int s = 0; s < 4; ++s) { \
            _Pragma("unroll") \
            for (int mf = 0; mf < 2; ++mf) \
                ldsm_x4(ah[mf], base + SM_A + swz8(arow_f + mf * 16, 2 * s + l16)); \
            _Pragma("unroll") \
            for (int nb = 0; nb < 2; ++nb) \
                ldsm_x4(bb[nb], base + SM_B + swz8(brow + nb * 16, 2 * s + bch)); \
            _Pragma("unroll") \
            for (int mf = 0; mf < 2; ++mf) \
                _Pragma("unroll") \
                for (int nf = 0; nf < 4; ++nf) \
                    mma_f16(acc[mf][nf], ah[mf], &bb[nf >> 1][(nf & 1) * 2]); \
        } \
    } \
} while (0)

// ---------------------------------------------------------------------------
// k_main: flat grid of exactly total_f + total_p CTAs, proportionally
// interleaved (Bresenham): fgemm f-index fa when floor-count increments,
// else P-job (pi % 6 -> which of ig0..3 / o0..1; pi / 6 -> tile).
//   fgemm : fc[seg[e]] += sig(hs@Wf + bf) * cc     (atomics)
//   ig    : ig = sig(i)*tanh(g)   -> fp16
//   o     : oact = sig(o + b)     -> fp16
// ---------------------------------------------------------------------------
__global__ void __launch_bounds__(256, 3)
k_main(const __half* __restrict__ hs16, const __half* __restrict__ sum16,
       const __half* __restrict__ wf, const __half* __restrict__ wig,
       const __half* __restrict__ wo,
       const float* __restrict__ bf, const float* __restrict__ bg,
       const float* __restrict__ cc, const int* __restrict__ seg,
       float* __restrict__ fc, __half* __restrict__ ig, __half* __restrict__ oact,
       int E, int P, int total_f, int total) {
    const int i = blockIdx.x;
    const long long fa = (long long)i * total_f / total;
    const long long fb = (long long)(i + 1) * total_f / total;
    int kind, nsel, tile;
    if (fb > fa) {                       // fgemm CTA
        int f = (int)fa;
        kind = 0; nsel = f & 1; tile = f >> 1;
    } else {                             // P-job CTA
        int pi = i - (int)fa;
        int pj = pi % 6;
        tile = pi / 6;
        if (pj < 4) { kind = 1; nsel = pj; }
        else        { kind = 2; nsel = pj - 4; }
    }

    extern __shared__ char smem[];
    const uint32_t sb = smem_to_u32(smem);
    const int tid  = threadIdx.x;
    const int lane = tid & 31;
    const int wid  = tid >> 5;
    const int wm   = wid >> 2;
    const int wn   = wid & 3;
    const int bm   = tile * 64;

    const __half* A16 = (kind == 0) ? hs16 : sum16;
    const __half* Bt  = ((kind == 0) ? wf : (kind == 1 ? wig : wo))
                        + (size_t)nsel * 128 * D;
    const int Mtot    = (kind == 0) ? E : P;

    float acc[2][4][4];
    #pragma unroll
    for (int a = 0; a < 2; ++a)
        #pragma unroll
        for (int j = 0; j < 4; ++j)
            #pragma unroll
            for (int q = 0; q < 4; ++q) acc[a][j][q] = 0.f;

    const int l7  = lane & 7;
    const int l8  = (lane >> 3) & 1;
    const int l16 = lane >> 4;
    const int arow_f = wm * 32 + l8 * 8 + l7;
    const int brow   = wn * 32 + (lane & 7) + ((lane >> 4) << 3);
    const int bch    = (lane >> 3) & 1;

    GEMM_MAIN(A16, Bt, bm, Mtot);

    // ---- epilogue ----
    if (kind == 0) {
        float2 bias2[4];
        #pragma unroll
        for (int nf = 0; nf < 4; ++nf)
            bias2[nf] = *(const float2*)(bf + nsel * 128 + wn * 32 + nf * 8 + 2 * (lane & 3));
        #pragma unroll
        for (int mf = 0; mf < 2; ++mf) {
            #pragma unroll
            for (int half = 0; half < 2; ++half) {
                int r = bm + wm * 32 + mf * 16 + (lane >> 2) + half * 8;
                if (r >= Mtot) continue;
                int sid = seg[r];
                #pragma unroll
                for (int nf = 0; nf < 4; ++nf) {
                    int cn = nsel * 128 + wn * 32 + nf * 8 + 2 * (lane & 3);
                    float v0 = acc[mf][nf][half * 2 + 0] + bias2[nf].x;
                    float v1 = acc[mf][nf][half * 2 + 1] + bias2[nf].y;
                    size_t o = (size_t)r * D + cn;
                    float2 ccv = *(const float2*)(cc + o);
                    float* dst = fc + (size_t)sid * D + cn;
                    atomicAdd(dst,     sigmoid_f(v0) * ccv.x);
                    atomicAdd(dst + 1, sigmoid_f(v1) * ccv.y);
                }
            }
        }
    } else if (kind == 1) {
        int ocbase = (nsel * 4 + wn) * 16 + 2 * (lane & 3);
        float2 bi[2], bgv[2];
        #pragma unroll
        for (int nf = 0; nf < 2; ++nf) {
            bi[nf]  = *(const float2*)(bg + ocbase + nf * 8);
            bgv[nf] = *(const float2*)(bg + 512 + ocbase + nf * 8);
        }
        #pragma unroll
        for (int mf = 0; mf < 2; ++mf) {
            #pragma unroll
            for (int half = 0; half < 2; ++half) {
                int r = bm + wm * 32 + mf * 16 + (lane >> 2) + half * 8;
                if (r >= Mtot) continue;
                #pragma unroll
                for (int nf = 0; nf < 2; ++nf) {
                    int oc = ocbase + nf * 8;
                    float i0 = sigmoid_f(acc[mf][nf][half * 2 + 0] + bi[nf].x);
                    float i1 = sigmoid_f(acc[mf][nf][half * 2 + 1] + bi[nf].y);
                    float g0 = tanhf(acc[mf][nf + 2][half * 2 + 0] + bgv[nf].x);
                    float g1 = tanhf(acc[mf][nf + 2][half * 2 + 1] + bgv[nf].y);
                    *(__half2*)(ig + (size_t)r * D + oc) =
                        __floats2half2_rn(i0 * g0, i1 * g1);
                }
            }
        }
    } else {
        float2 bias2[4];
        #pragma unroll
        for (int nf = 0; nf < 4; ++nf)
            bias2[nf] = *(const float2*)(bg + 256 + nsel * 128 + wn * 32 + nf * 8 + 2 * (lane & 3));
        #pragma unroll
        for (int mf = 0; mf < 2; ++mf) {
            #pragma unroll
            for (int half = 0; half < 2; ++half) {
                int r = bm + wm * 32 + mf * 16 + (lane >> 2) + half * 8;
                if (r >= Mtot) continue;
                #pragma unroll
                for (int nf = 0; nf < 4; ++nf) {
                    int cn = nsel * 128 + wn * 32 + nf * 8 + 2 * (lane & 3);
                    float v0 = acc[mf][nf][half * 2 + 0] + bias2[nf].x;
                    float v1 = acc[mf][nf][half * 2 + 1] + bias2[nf].y;
                    *(__half2*)(oact + (size_t)r * D + cn) =
                        __floats2half2_rn(sigmoid_f(v0), sigmoid_f(v1));
                }
            }
        }
    }
}

// ---------------------------------------------------------------------------
// k_elem: c = ig + fc; h = oact * tanh(c)  (ig/oact fp16, 4 elems/thread)
// ---------------------------------------------------------------------------
__global__ void k_elem(const __half* __restrict__ oact, const __half* __restrict__ ig,
                       const float* __restrict__ fc, float* __restrict__ out,
                       int total) {
    int i4 = blockIdx.x * blockDim.x + threadIdx.x;
    if (i4 * 4 < total) {
        size_t idx = (size_t)i4 * 4;
        __half2 o01 = *(const __half2*)(oact + idx);
        __half2 o23 = *(const __half2*)(oact + idx + 2);
        __half2 g01 = *(const __half2*)(ig + idx);
        __half2 g23 = *(const __half2*)(ig + idx + 2);
        float4 fv = *(const float4*)(fc + idx);
        float2 of01 = __half22float2(o01), of23 = __half22float2(o23);
        float2 gf01 = __half22float2(g01), gf23 = __half22float2(g23);
        float4 c = make_float4(gf01.x + fv.x, gf01.y + fv.y,
                               gf23.x + fv.z, gf23.y + fv.w);
        float4 h = make_float4(of01.x * tanhf(c.x), of01.y * tanhf(c.y),
                               of23.x * tanhf(c.z), of23.y * tanhf(c.w));
        *(float4*)(out + idx) = h;
        *(float4*)(out + (size_t)total + idx) = c;
    }
}

// ---------------------------------------------------------------------------
extern "C" void kernel_launch(void* const* d_in, const int* in_sizes, int n_in,
                              void* d_out, int out_size) {
    const float* child_hs = (const float*)d_in[0];
    const float* child_cs = (const float*)d_in[1];
    const int*   seg      = (const int*)d_in[2];
    const float* Wg = (const float*)d_in[4];
    const float* bg = (const float*)d_in[5];
    const float* Wf = (const float*)d_in[6];
    const float* bf = (const float*)d_in[7];
    (void)n_in;

    int E = in_sizes[2];
    int P = out_size / (2 * D);
    if (P > MAX_P) P = MAX_P;
    if (E > MAX_E) E = MAX_E;

    float* out = (float*)d_out;

    static bool inited = false;
    static float *fc_p;
    static __half *ig_p, *oa_p, *hs16_p, *sum16_p, *wf_p, *wig_p, *wo_p;
    if (!inited) {
        cudaGetSymbolAddress((void**)&fc_p,    g_fc);
        cudaGetSymbolAddress((void**)&ig_p,    g_ig);
        cudaGetSymbolAddress((void**)&oa_p,    g_oact);
        cudaGetSymbolAddress((void**)&hs16_p,  g_hs16);
        cudaGetSymbolAddress((void**)&sum16_p, g_hssum16);
        cudaGetSymbolAddress((void**)&wf_p,    g_wf16);
        cudaGetSymbolAddress((void**)&wig_p,   g_wig16);
        cudaGetSymbolAddress((void**)&wo_p,    g_wo16);
        cudaFuncSetAttribute(k_main, cudaFuncAttributeMaxDynamicSharedMemorySize, SM_TOTAL);
        inited = true;
    }

    int etiles = (E + 63) / 64;
    int ptiles = (P + 63) / 64;
    int total_f = 2 * etiles;
    int total_p = 6 * ptiles;
    int total   = total_f + total_p;

    // prep: weight transposes + segment sum, one co-scheduled launch
    k_prep<<<256 + (P + 15) / 16, 256>>>(
        Wf, Wg, child_hs, seg, E, P,
        wf_p, wig_p, wo_p, hs16_p, sum16_p, fc_p);

    // all three GEMMs, exact interleaved flat grid
    k_main<<<total, 256, SM_TOTAL>>>(
        hs16_p, sum16_p, wf_p, wig_p, wo_p, bf, bg, child_cs, seg,
        fc_p, ig_p, oa_p, E, P, total_f, total);

    // elementwise final combine
    k_elem<<<(P * D / 4 + 255) / 256, 256>>>(oa_p, ig_p, fc_p, out, P * D);
}